// round 2
// baseline (speedup 1.0000x reference)
#include <cuda_runtime.h>
#include <math.h>

#define BB  2
#define CIN 512
#define CC  256
#define HH  48
#define WW  48
#define HWW 2304
#define LL  2304
#define DI  512
#define BL  (BB*LL)
#define BNF 0.9999950000374997f   /* 1/sqrt(1+1e-5) */

// ------------------------- static scratch (no allocs) -------------------------
__device__ __align__(256) float g_xred[BB*CC*HWW];
__device__ __align__(256) float g_p[BB*CC*HWW];
__device__ __align__(256) float g_hv[BB*CC*HWW];
__device__ __align__(256) float g_featloc[BB*CC*HWW];
__device__ __align__(256) float g_featglob[BB*CC*HWW];
__device__ __align__(256) float g_mu[BB*HWW];
__device__ __align__(256) float g_rstd[BB*HWW];
__device__ __align__(256) float g_xn[BL*CC];          // (b,l,c)
__device__ __align__(256) float g_xz[BL*2*DI];        // (b,l,1024): xm0 | z
__device__ __align__(256) float g_xm[4*BL*DI];        // (dir,b,l,d) post conv+silu
__device__ __align__(256) float g_projm[4*BL*48];     // (dir,b,l,48)
__device__ __align__(256) float g_dtb[4*BL*DI];
__device__ __align__(256) float g_y[4*BL*DI];
__device__ __align__(256) float g_ysum[BL*DI];
__device__ __align__(256) float g_sv[BB*CC];
__device__ __align__(256) float g_wv[BB*2*CC];

__device__ __forceinline__ int seq_map(int dir, int t) {
    if (dir == 0) return t;
    if (dir == 1) return LL - 1 - t;
    int u = (dir == 2) ? t : (LL - 1 - t);
    int h = u % HH, w = u / HH;
    return h * WW + w;
}

__device__ __forceinline__ float silu_f(float x) { return x / (1.f + __expf(-x)); }

// ------------------------- GEMM NN: C[m,n] = f(sum_k A[m,k]B[k,n]) ------------
// A: MxK rowmajor (weights). B: KxN rowmajor (data). Requires M%64==0,N%64==0,K%16==0.
template<int MODE>
__global__ void __launch_bounds__(256) gemm_nn_k(
    const float* __restrict__ A, const float* __restrict__ B, float* __restrict__ C,
    int M, int N, int K, long long sB, long long sC,
    const float* __restrict__ scale, const float* __restrict__ bias)
{
    __shared__ float As[16][68];
    __shared__ float Bs[16][68];
    const float* Bb = B + (long long)blockIdx.z * sB;
    float* Cb = C + (long long)blockIdx.z * sC;
    int tid = threadIdx.x;
    int tx = tid & 15, ty = tid >> 4;
    int m0 = blockIdx.y * 64, n0 = blockIdx.x * 64;
    int la_m = tid >> 2, la_k = (tid & 3) << 2;
    int lb_k = tid >> 4, lb_n = (tid & 15) << 2;
    float acc[4][4] = {};
    for (int k0 = 0; k0 < K; k0 += 16) {
        float4 av = *(const float4*)(A + (long long)(m0 + la_m) * K + k0 + la_k);
        As[la_k + 0][la_m] = av.x; As[la_k + 1][la_m] = av.y;
        As[la_k + 2][la_m] = av.z; As[la_k + 3][la_m] = av.w;
        float4 bv = *(const float4*)(Bb + (long long)(k0 + lb_k) * N + n0 + lb_n);
        *(float4*)&Bs[lb_k][lb_n] = bv;
        __syncthreads();
#pragma unroll
        for (int k = 0; k < 16; k++) {
            float4 a4 = *(const float4*)&As[k][ty * 4];
            float4 b4 = *(const float4*)&Bs[k][tx * 4];
            float a[4] = {a4.x, a4.y, a4.z, a4.w};
            float b[4] = {b4.x, b4.y, b4.z, b4.w};
#pragma unroll
            for (int i = 0; i < 4; i++)
#pragma unroll
                for (int j = 0; j < 4; j++) acc[i][j] += a[i] * b[j];
        }
        __syncthreads();
    }
#pragma unroll
    for (int i = 0; i < 4; i++) {
        int m = m0 + ty * 4 + i;
        float sc = 0.f, bi = 0.f;
        if (MODE == 1) { sc = scale[m] * BNF; bi = bias[m]; }
        if (MODE == 2) { bi = bias[m]; }
        float4 o;
        float v[4];
#pragma unroll
        for (int j = 0; j < 4; j++) {
            float t = acc[i][j];
            if (MODE == 1) t = fmaxf(t * sc + bi, 0.f);
            else if (MODE == 2) t = t + bi;
            v[j] = t;
        }
        o.x = v[0]; o.y = v[1]; o.z = v[2]; o.w = v[3];
        *(float4*)(Cb + (long long)m * N + n0 + tx * 4) = o;
    }
}

// ------------------------- GEMM NT: C[m,n] = f(sum_k A[m,k]B[n,k]) ------------
// Both rowmajor with K contiguous. Requires M%64==0, K%16==0; N guarded.
template<int MODE>
__global__ void __launch_bounds__(256) gemm_nt_k(
    const float* __restrict__ A, const float* __restrict__ B, float* __restrict__ C,
    int M, int N, int K, long long sA, long long sB, long long sC,
    const float* __restrict__ extra, long long sE)
{
    __shared__ float As[16][68];
    __shared__ float Bs[16][68];
    const float* Ab = A + (long long)blockIdx.z * sA;
    const float* Bb = B + (long long)blockIdx.z * sB;
    float* Cb = C + (long long)blockIdx.z * sC;
    int tid = threadIdx.x;
    int tx = tid & 15, ty = tid >> 4;
    int m0 = blockIdx.y * 64, n0 = blockIdx.x * 64;
    int lm = tid >> 2, lk = (tid & 3) << 2;
    float acc[4][4] = {};
    for (int k0 = 0; k0 < K; k0 += 16) {
        float4 av = *(const float4*)(Ab + (long long)(m0 + lm) * K + k0 + lk);
        As[lk + 0][lm] = av.x; As[lk + 1][lm] = av.y;
        As[lk + 2][lm] = av.z; As[lk + 3][lm] = av.w;
        int bn = n0 + lm;
        float4 bv = make_float4(0.f, 0.f, 0.f, 0.f);
        if (bn < N) bv = *(const float4*)(Bb + (long long)bn * K + k0 + lk);
        Bs[lk + 0][lm] = bv.x; Bs[lk + 1][lm] = bv.y;
        Bs[lk + 2][lm] = bv.z; Bs[lk + 3][lm] = bv.w;
        __syncthreads();
#pragma unroll
        for (int k = 0; k < 16; k++) {
            float4 a4 = *(const float4*)&As[k][ty * 4];
            float4 b4 = *(const float4*)&Bs[k][tx * 4];
            float a[4] = {a4.x, a4.y, a4.z, a4.w};
            float b[4] = {b4.x, b4.y, b4.z, b4.w};
#pragma unroll
            for (int i = 0; i < 4; i++)
#pragma unroll
                for (int j = 0; j < 4; j++) acc[i][j] += a[i] * b[j];
        }
        __syncthreads();
    }
#pragma unroll
    for (int i = 0; i < 4; i++) {
        int m = m0 + ty * 4 + i;
#pragma unroll
        for (int j = 0; j < 4; j++) {
            int n = n0 + tx * 4 + j;
            if (n < N) {
                float v = acc[i][j];
                if (MODE == 3)
                    v = v * 0.25f + extra[(long long)blockIdx.z * sE + (long long)m * N + n];
                Cb[(long long)m * N + n] = v;
            }
        }
    }
}

// ------------------------- depthwise 1x7 + 7x1 fused --------------------------
__global__ void dwconv_k(const float* __restrict__ p,
                         const float* __restrict__ wh, const float* __restrict__ wv,
                         const float* __restrict__ hg, const float* __restrict__ hb,
                         const float* __restrict__ vg, const float* __restrict__ vb,
                         float* __restrict__ out)
{
    int idx = blockIdx.x * blockDim.x + threadIdx.x;
    if (idx >= BB * CC * HWW) return;
    int l = idx % HWW;
    int c = (idx / HWW) % CC;
    int y = l / WW, x = l % WW;
    const float* base = p + (idx - l);
    float sh = 0.f, sv = 0.f;
#pragma unroll
    for (int j = 0; j < 7; j++) {
        int xx = x - 3 + j;
        if (xx >= 0 && xx < WW) sh += base[y * WW + xx] * wh[c * 7 + j];
        int yy = y - 3 + j;
        if (yy >= 0 && yy < HH) sv += base[yy * WW + x] * wv[c * 7 + j];
    }
    float rh = fmaxf(sh * (hg[c] * BNF) + hb[c], 0.f);
    float rv = fmaxf(sv * (vg[c] * BNF) + vb[c], 0.f);
    out[idx] = rh + rv;
}

// ------------------------- layernorm over C (stats + transpose/normalize) ----
__global__ void ln_stats_k(const float* __restrict__ x)
{
    int l = blockIdx.x * blockDim.x + threadIdx.x;
    int b = blockIdx.y;
    if (l >= HWW) return;
    const float* xp = x + (long long)b * CC * HWW + l;
    float s = 0.f, ss = 0.f;
#pragma unroll 8
    for (int c = 0; c < CC; c++) { float v = xp[(long long)c * HWW]; s += v; ss += v * v; }
    float mu = s * (1.f / CC);
    float var = ss * (1.f / CC) - mu * mu;
    g_mu[b * HWW + l] = mu;
    g_rstd[b * HWW + l] = rsqrtf(var + 1e-5f);
}

__global__ void trans_norm_k(const float* __restrict__ x,
                             const float* __restrict__ lng, const float* __restrict__ lnb)
{
    __shared__ float tile[32][33];
    int b = blockIdx.z;
    int l0 = blockIdx.x * 32, c0 = blockIdx.y * 32;
    int tx = threadIdx.x, ty = threadIdx.y;   // (32,8)
#pragma unroll
    for (int i = 0; i < 4; i++) {
        int c = c0 + ty + i * 8;
        tile[ty + i * 8][tx] = x[((long long)b * CC + c) * HWW + l0 + tx];
    }
    __syncthreads();
#pragma unroll
    for (int i = 0; i < 4; i++) {
        int l = l0 + ty + i * 8;
        int c = c0 + tx;
        float v = (tile[tx][ty + i * 8] - g_mu[b * HWW + l]) * g_rstd[b * HWW + l];
        g_xn[((long long)b * HWW + l) * CC + c] = v * lng[c] + lnb[c];
    }
}

// ------------------------- causal depthwise conv1d + silu (per direction) ----
__global__ void conv1d_k(const float* __restrict__ cw, const float* __restrict__ cb)
{
    int d = threadIdx.x;     // 512
    int t = blockIdx.x;      // L
    int b = blockIdx.y;      // B
    int dir = blockIdx.z;    // 4
    float w0 = cw[d * 4 + 0], w1 = cw[d * 4 + 1], w2 = cw[d * 4 + 2], w3 = cw[d * 4 + 3];
    float s = cb[d];
    long long bb = (long long)b * LL;
    if (t >= 3) s += g_xz[(bb + seq_map(dir, t - 3)) * 1024 + d] * w0;
    if (t >= 2) s += g_xz[(bb + seq_map(dir, t - 2)) * 1024 + d] * w1;
    if (t >= 1) s += g_xz[(bb + seq_map(dir, t - 1)) * 1024 + d] * w2;
    s += g_xz[(bb + seq_map(dir, t)) * 1024 + d] * w3;
    g_xm[(((long long)dir * BB + b) * LL + seq_map(dir, t)) * DI + d] = silu_f(s);
}

// ------------------------- dt = softplus(proj[:,:16] @ dt_w.T + dt_b) --------
__global__ void dt_k(const float* __restrict__ dtw, const float* __restrict__ dtbias)
{
    __shared__ float pr[16];
    int d = threadIdx.x;
    int l = blockIdx.x, b = blockIdx.y, dir = blockIdx.z;
    long long row = ((long long)dir * BB + b) * LL + l;
    if (d < 16) pr[d] = g_projm[row * 48 + d];
    __syncthreads();
    float acc = dtbias[d];
#pragma unroll
    for (int r = 0; r < 16; r++) acc += pr[r] * dtw[d * 16 + r];
    float dt = (acc > 15.f) ? acc : log1pf(expf(acc));
    g_dtb[row * DI + d] = dt;
}

// ------------------------- selective scan -------------------------------------
// warp = 2 channels x 16 states; 4-deep software prefetch to hide L2 latency.
__global__ void __launch_bounds__(256) scan_k(const float* __restrict__ A_log,
                                              const float* __restrict__ Dp)
{
    int tid = threadIdx.x;
    int lane = tid & 31;
    int gwarp = blockIdx.x * 8 + (tid >> 5);          // 0..2047
    int dir = gwarp >> 9;
    int b = (gwarp >> 8) & 1;
    int d = ((gwarp & 255) << 1) | (lane >> 4);
    int s = lane & 15;

    float Av = -expf(A_log[d * 16 + s]);
    float Dv = Dp[d];
    long long dbase = ((long long)dir * BB + b) * LL;
    const float* dtp = g_dtb + dbase * DI;
    const float* xmp = g_xm + dbase * DI;
    const float* prp = g_projm + dbase * 48;
    const float* zp = g_xz + (long long)b * LL * 1024 + DI;
    float* yp = g_y + dbase * DI;

    const int PF = 4;
    int lbuf[PF];
    float f_dt[PF], f_x[PF], f_B[PF], f_C[PF], f_z[PF];
#pragma unroll
    for (int i = 0; i < PF; i++) {
        int l = seq_map(dir, i);
        lbuf[i] = l;
        f_dt[i] = dtp[(long long)l * DI + d];
        f_x[i]  = xmp[(long long)l * DI + d];
        f_B[i]  = prp[(long long)l * 48 + 16 + s];
        f_C[i]  = prp[(long long)l * 48 + 32 + s];
        f_z[i]  = zp[(long long)l * 1024 + d];
    }
    float h = 0.f;
    for (int t0 = 0; t0 < LL; t0 += PF) {
#pragma unroll
        for (int i = 0; i < PF; i++) {
            int t = t0 + i;
            float dtv = f_dt[i], xv = f_x[i], Bv = f_B[i], Cv = f_C[i], zv = f_z[i];
            int l = lbuf[i];
            int tn = t + PF;
            if (tn < LL) {
                int ln = seq_map(dir, tn);
                lbuf[i] = ln;
                f_dt[i] = dtp[(long long)ln * DI + d];
                f_x[i]  = xmp[(long long)ln * DI + d];
                f_B[i]  = prp[(long long)ln * 48 + 16 + s];
                f_C[i]  = prp[(long long)ln * 48 + 32 + s];
                f_z[i]  = zp[(long long)ln * 1024 + d];
            }
            float dA = __expf(dtv * Av);
            h = dA * h + dtv * xv * Bv;
            float part = h * Cv;
            part += __shfl_xor_sync(0xffffffffu, part, 1);
            part += __shfl_xor_sync(0xffffffffu, part, 2);
            part += __shfl_xor_sync(0xffffffffu, part, 4);
            part += __shfl_xor_sync(0xffffffffu, part, 8);
            if (s == 0) {
                float yv = (part + Dv * xv) * silu_f(zv);
                yp[(long long)l * DI + d] = yv;
            }
        }
    }
}

// ------------------------- sum gated y over the 4 directions ------------------
__global__ void ysum_k()
{
    long long i = (long long)blockIdx.x * blockDim.x + threadIdx.x;
    if (i < (long long)BL * DI) {
        const long long st = (long long)BL * DI;
        g_ysum[i] = g_y[i] + g_y[i + st] + g_y[i + 2 * st] + g_y[i + 3 * st];
    }
}

// ------------------------- SE head --------------------------------------------
__global__ void mean_k()
{
    int c = blockIdx.x, b = blockIdx.y;
    long long base = ((long long)b * CC + c) * HWW;
    float s = 0.f;
    for (int l = threadIdx.x; l < HWW; l += 256)
        s += g_featloc[base + l] + g_featglob[base + l];
    __shared__ float red[256];
    red[threadIdx.x] = s;
    __syncthreads();
    for (int o = 128; o; o >>= 1) {
        if (threadIdx.x < o) red[threadIdx.x] += red[threadIdx.x + o];
        __syncthreads();
    }
    if (threadIdx.x == 0) g_sv[b * CC + c] = red[0] / (float)HWW;
}

__global__ void fc_k(const float* __restrict__ fc1, const float* __restrict__ fc2)
{
    int b = blockIdx.x;
    __shared__ float ss[CC], tt[16];
    int tid = threadIdx.x;   // 256
    ss[tid] = g_sv[b * CC + tid];
    __syncthreads();
    if (tid < 16) {
        float a = 0.f;
        for (int c = 0; c < CC; c++) a += ss[c] * fc1[tid * CC + c];
        tt[tid] = fmaxf(a, 0.f);
    }
    __syncthreads();
    float z0 = 0.f, z1 = 0.f;
#pragma unroll
    for (int m = 0; m < 16; m++) {
        z0 += tt[m] * fc2[tid * 16 + m];
        z1 += tt[m] * fc2[(CC + tid) * 16 + m];
    }
    float mx = fmaxf(z0, z1);
    float e0 = expf(z0 - mx), e1 = expf(z1 - mx);
    float w0 = e0 / (e0 + e1);
    g_wv[b * 2 * CC + tid] = w0;
    g_wv[b * 2 * CC + CC + tid] = 1.f - w0;
}

__global__ void final_k(float* __restrict__ out)
{
    long long i = (long long)blockIdx.x * 256 + threadIdx.x;
    if (i >= (long long)BB * CC * HWW) return;
    int c = (int)((i / HWW) % CC);
    int b = (int)(i / ((long long)CC * HWW));
    out[i] = g_wv[b * 2 * CC + c] * g_featloc[i] + g_wv[b * 2 * CC + CC + c] * g_featglob[i];
}

// ------------------------- launch ---------------------------------------------
extern "C" void kernel_launch(void* const* d_in, const int* in_sizes, int n_in,
                              void* d_out, int out_size)
{
    const float* x        = (const float*)d_in[0];
    const float* reduce_w = (const float*)d_in[1];
    const float* bn0_g    = (const float*)d_in[2];
    const float* bn0_b    = (const float*)d_in[3];
    const float* proj_w   = (const float*)d_in[4];
    const float* bn1_g    = (const float*)d_in[5];
    const float* bn1_b    = (const float*)d_in[6];
    const float* dwh_w    = (const float*)d_in[7];
    const float* bnh_g    = (const float*)d_in[8];
    const float* bnh_b    = (const float*)d_in[9];
    const float* dwv_w    = (const float*)d_in[10];
    const float* bnv_g    = (const float*)d_in[11];
    const float* bnv_b    = (const float*)d_in[12];
    const float* fus_w    = (const float*)d_in[13];
    const float* fus_b    = (const float*)d_in[14];
    const float* ln_g     = (const float*)d_in[15];
    const float* ln_b     = (const float*)d_in[16];
    const float* in_w     = (const float*)d_in[17];
    const float* conv_w   = (const float*)d_in[18];
    const float* conv_b   = (const float*)d_in[19];
    const float* xproj_w  = (const float*)d_in[20];
    const float* dt_w     = (const float*)d_in[21];
    const float* dt_b     = (const float*)d_in[22];
    const float* A_log    = (const float*)d_in[23];
    const float* Dp       = (const float*)d_in[24];
    const float* out_w    = (const float*)d_in[25];
    const float* fc1_w    = (const float*)d_in[26];
    const float* fc2_w    = (const float*)d_in[27];

    float *xred, *p, *hv, *featloc, *featglob, *xn, *xz, *xm, *projm, *ysum;
    cudaGetSymbolAddress((void**)&xred, g_xred);
    cudaGetSymbolAddress((void**)&p, g_p);
    cudaGetSymbolAddress((void**)&hv, g_hv);
    cudaGetSymbolAddress((void**)&featloc, g_featloc);
    cudaGetSymbolAddress((void**)&featglob, g_featglob);
    cudaGetSymbolAddress((void**)&xn, g_xn);
    cudaGetSymbolAddress((void**)&xz, g_xz);
    cudaGetSymbolAddress((void**)&xm, g_xm);
    cudaGetSymbolAddress((void**)&projm, g_projm);
    cudaGetSymbolAddress((void**)&ysum, g_ysum);

    // 1) x = relu(bn0(reduce_w @ xin))   (per-b GEMM, channel-major out)
    gemm_nn_k<1><<<dim3(36, 4, BB), 256>>>(reduce_w, x, xred, 256, 2304, 512,
                                           (long long)CIN * HWW, (long long)CC * HWW,
                                           bn0_g, bn0_b);
    // 2) p = relu(bn1(proj_w @ x))
    gemm_nn_k<1><<<dim3(36, 4, BB), 256>>>(proj_w, xred, p, 256, 2304, 256,
                                           (long long)CC * HWW, (long long)CC * HWW,
                                           bn1_g, bn1_b);
    // 3) h+v depthwise branches fused
    dwconv_k<<<(BB * CC * HWW + 255) / 256, 256>>>(p, dwh_w, dwv_w,
                                                   bnh_g, bnh_b, bnv_g, bnv_b, hv);
    // 4) feat_local = fus_w @ (h+v) + fus_b
    gemm_nn_k<2><<<dim3(36, 4, BB), 256>>>(fus_w, hv, featloc, 256, 2304, 256,
                                           (long long)CC * HWW, (long long)CC * HWW,
                                           (const float*)0, fus_b);
    // 5) layernorm over C (shared by all 4 directions)
    ln_stats_k<<<dim3((HWW + 255) / 256, BB), 256>>>(xred);
    trans_norm_k<<<dim3(HWW / 32, CC / 32, BB), dim3(32, 8)>>>(xred, ln_g, ln_b);
    // 6) in_proj: xz = xn @ in_w.T  (shared by all directions)
    gemm_nt_k<0><<<dim3(16, 36, BB), 256>>>(xn, in_w, xz, 2304, 1024, 256,
                                            (long long)LL * CC, 0, (long long)LL * 1024,
                                            (const float*)0, 0);
    // 7) causal conv1d + silu, all 4 directions
    conv1d_k<<<dim3(LL, BB, 4), 512>>>(conv_w, conv_b);
    // 8) xproj per direction: proj = xm @ xproj_w.T
    gemm_nt_k<0><<<dim3(1, 36, 8), 256>>>(xm, xproj_w, projm, 2304, 48, 512,
                                          (long long)LL * DI, 0, (long long)LL * 48,
                                          (const float*)0, 0);
    // 9) dt = softplus(...)
    dt_k<<<dim3(LL, BB, 4), 512>>>(dt_w, dt_b);
    // 10) selective scan, all 4 directions concurrently
    scan_k<<<256, 256>>>(A_log, Dp);
    // 11) sum gated y over directions (out_proj is linear)
    ysum_k<<<(BL * DI + 255) / 256, 256>>>();
    // 12) feat_global = 0.25 * (out_w @ ysum) + x
    gemm_nt_k<3><<<dim3(36, 4, BB), 256>>>(out_w, ysum, featglob, 256, 2304, 512,
                                           0, (long long)LL * DI, (long long)CC * HWW,
                                           xred, (long long)CC * HWW);
    // 13) SE head + final combine
    mean_k<<<dim3(CC, BB), 256>>>();
    fc_k<<<BB, 256>>>(fc1_w, fc2_w);
    final_k<<<(BB * CC * HWW + 255) / 256, 256>>>((float*)d_out);
}

// round 3
// speedup vs baseline: 1.6151x; 1.6151x over previous
#include <cuda_runtime.h>
#include <math.h>

#define BB  2
#define CIN 512
#define CC  256
#define HH  48
#define WW  48
#define HWW 2304
#define LL  2304
#define DI  512
#define BL  (BB*LL)
#define BNF 0.9999950000374997f   /* 1/sqrt(1+1e-5) */

// ------------------------- static scratch (no allocs) -------------------------
__device__ __align__(256) float g_xred[BB*CC*HWW];
__device__ __align__(256) float g_p[BB*CC*HWW];
__device__ __align__(256) float g_hv[BB*CC*HWW];
__device__ __align__(256) float g_featloc[BB*CC*HWW];
__device__ __align__(256) float g_featglob[BB*CC*HWW];
__device__ __align__(256) float g_mu[BB*HWW];
__device__ __align__(256) float g_rstd[BB*HWW];
__device__ __align__(256) float g_xn[BL*CC];          // (b,l,c)
__device__ __align__(256) float g_xz[BL*2*DI];        // (b,l,1024): xm0 | z
__device__ __align__(256) float g_xm[4*BL*DI];        // (dir,b,t,d) SCAN order
__device__ __align__(256) float g_projm[4*BL*48];     // (dir,b,t,48) SCAN order
__device__ __align__(256) float g_dtb[4*BL*DI];       // SCAN order
__device__ __align__(256) float g_y[4*BL*DI];         // SCAN order, ungated
__device__ __align__(256) float g_ysum[BL*DI];        // natural order, gated
__device__ __align__(256) float g_sv[BB*CC];
__device__ __align__(256) float g_wv[BB*2*CC];

__device__ __forceinline__ int seq_map(int dir, int t) {
    if (dir == 0) return t;
    if (dir == 1) return LL - 1 - t;
    int u = (dir == 2) ? t : (LL - 1 - t);
    int h = u % HH, w = u / HH;
    return h * WW + w;
}

__device__ __forceinline__ float silu_f(float x) { return x / (1.f + __expf(-x)); }

// ------------------------- 128x64 SGEMM -----------------------------------
// C[m,n] = f(sum_k A[m,k] * B[k,n])   (TB=false: B is KxN rowmajor)
// C[m,n] = f(sum_k A[m,k] * B[n,k])   (TB=true:  B is NxK rowmajor)
// Requires M%128==0, K%16==0. N%64==0 unless TB (then guarded).
template<int MODE, bool TB>
__global__ void __launch_bounds__(256) gemm128(
    const float* __restrict__ A, const float* __restrict__ B, float* __restrict__ C,
    int M, int N, int K,
    long long sA, long long sB, long long sC,
    const float* __restrict__ scale, const float* __restrict__ bias,
    const float* __restrict__ extra, long long sE)
{
    __shared__ float As[16][132];
    __shared__ float Bs[16][68];
    const float* Ab = A + (long long)blockIdx.z * sA;
    const float* Bb = B + (long long)blockIdx.z * sB;
    float* Cb = C + (long long)blockIdx.z * sC;
    int tid = threadIdx.x;
    int m0 = blockIdx.y * 128, n0 = blockIdx.x * 64;
    int tx = tid & 15, ty = tid >> 4;

    int am = tid >> 1;            // 0..127
    int ak = (tid & 1) * 8;       // 0 or 8
    int bn, bk;
    if (TB) { bn = tid >> 2; bk = (tid & 3) * 4; }   // 64 rows x 16 k
    else    { bk = tid >> 4; bn = (tid & 15) * 4; }  // 16 k x 64 n

    const float* Aptr = Ab + (long long)(m0 + am) * K + ak;
    const float* Bptr;
    bool bvalid = true;
    if (TB) {
        bvalid = (n0 + bn) < N;
        Bptr = Bb + (long long)(n0 + bn) * K + bk;
    } else {
        Bptr = Bb + (long long)bk * N + n0 + bn;
    }

    float4 pa0 = *(const float4*)(Aptr);
    float4 pa1 = *(const float4*)(Aptr + 4);
    float4 pb = make_float4(0.f, 0.f, 0.f, 0.f);
    if (!TB || bvalid) pb = *(const float4*)(Bptr);

    float acc[8][4] = {};

    for (int k0 = 0; k0 < K; k0 += 16) {
        As[ak+0][am]=pa0.x; As[ak+1][am]=pa0.y; As[ak+2][am]=pa0.z; As[ak+3][am]=pa0.w;
        As[ak+4][am]=pa1.x; As[ak+5][am]=pa1.y; As[ak+6][am]=pa1.z; As[ak+7][am]=pa1.w;
        if (TB) {
            Bs[bk+0][bn]=pb.x; Bs[bk+1][bn]=pb.y; Bs[bk+2][bn]=pb.z; Bs[bk+3][bn]=pb.w;
        } else {
            *(float4*)&Bs[bk][bn] = pb;
        }
        __syncthreads();
        if (k0 + 16 < K) {
            Aptr += 16;
            pa0 = *(const float4*)(Aptr);
            pa1 = *(const float4*)(Aptr + 4);
            if (TB) { Bptr += 16; if (bvalid) pb = *(const float4*)(Bptr); }
            else    { Bptr += (long long)16 * N; pb = *(const float4*)(Bptr); }
        }
#pragma unroll
        for (int k = 0; k < 16; k++) {
            float4 a0 = *(const float4*)&As[k][ty*8];
            float4 a1 = *(const float4*)&As[k][ty*8+4];
            float4 b4 = *(const float4*)&Bs[k][tx*4];
            float a[8] = {a0.x,a0.y,a0.z,a0.w,a1.x,a1.y,a1.z,a1.w};
            float bb[4] = {b4.x,b4.y,b4.z,b4.w};
#pragma unroll
            for (int i = 0; i < 8; i++)
#pragma unroll
                for (int j = 0; j < 4; j++)
                    acc[i][j] = fmaf(a[i], bb[j], acc[i][j]);
        }
        __syncthreads();
    }

#pragma unroll
    for (int i = 0; i < 8; i++) {
        int m = m0 + ty*8 + i;
        float sc = 1.f, bi = 0.f;
        if (MODE == 1) { sc = scale[m] * BNF; bi = bias[m]; }
        if (MODE == 2) { bi = bias[m]; }
        int n = n0 + tx*4;
        if (!TB || n + 3 < N) {
            float v[4];
#pragma unroll
            for (int j = 0; j < 4; j++) {
                float t = acc[i][j];
                if (MODE == 1) t = fmaxf(fmaf(t, sc, bi), 0.f);
                else if (MODE == 2) t = t + bi;
                else if (MODE == 3)
                    t = t * 0.25f + extra[(long long)blockIdx.z * sE + (long long)m * N + n + j];
                v[j] = t;
            }
            float4 o = make_float4(v[0], v[1], v[2], v[3]);
            *(float4*)(Cb + (long long)m * N + n) = o;
        }
    }
}

// ------------------------- depthwise 1x7 + 7x1 fused --------------------------
__global__ void dwconv_k(const float* __restrict__ p,
                         const float* __restrict__ wh, const float* __restrict__ wv,
                         const float* __restrict__ hg, const float* __restrict__ hb,
                         const float* __restrict__ vg, const float* __restrict__ vb,
                         float* __restrict__ out)
{
    int idx = blockIdx.x * blockDim.x + threadIdx.x;
    if (idx >= BB * CC * HWW) return;
    int l = idx % HWW;
    int c = (idx / HWW) % CC;
    int y = l / WW, x = l % WW;
    const float* base = p + (idx - l);
    float sh = 0.f, sv = 0.f;
#pragma unroll
    for (int j = 0; j < 7; j++) {
        int xx = x - 3 + j;
        if (xx >= 0 && xx < WW) sh += base[y * WW + xx] * wh[c * 7 + j];
        int yy = y - 3 + j;
        if (yy >= 0 && yy < HH) sv += base[yy * WW + x] * wv[c * 7 + j];
    }
    float rh = fmaxf(sh * (hg[c] * BNF) + hb[c], 0.f);
    float rv = fmaxf(sv * (vg[c] * BNF) + vb[c], 0.f);
    out[idx] = rh + rv;
}

// ------------------------- layernorm over C -----------------------------------
__global__ void ln_stats_k(const float* __restrict__ x)
{
    int l = blockIdx.x * blockDim.x + threadIdx.x;
    int b = blockIdx.y;
    if (l >= HWW) return;
    const float* xp = x + (long long)b * CC * HWW + l;
    float s = 0.f, ss = 0.f;
#pragma unroll 8
    for (int c = 0; c < CC; c++) { float v = xp[(long long)c * HWW]; s += v; ss += v * v; }
    float mu = s * (1.f / CC);
    float var = ss * (1.f / CC) - mu * mu;
    g_mu[b * HWW + l] = mu;
    g_rstd[b * HWW + l] = rsqrtf(var + 1e-5f);
}

__global__ void trans_norm_k(const float* __restrict__ x,
                             const float* __restrict__ lng, const float* __restrict__ lnb)
{
    __shared__ float tile[32][33];
    int b = blockIdx.z;
    int l0 = blockIdx.x * 32, c0 = blockIdx.y * 32;
    int tx = threadIdx.x, ty = threadIdx.y;   // (32,8)
#pragma unroll
    for (int i = 0; i < 4; i++) {
        int c = c0 + ty + i * 8;
        tile[ty + i * 8][tx] = x[((long long)b * CC + c) * HWW + l0 + tx];
    }
    __syncthreads();
#pragma unroll
    for (int i = 0; i < 4; i++) {
        int l = l0 + ty + i * 8;
        int c = c0 + tx;
        float v = (tile[tx][ty + i * 8] - g_mu[b * HWW + l]) * g_rstd[b * HWW + l];
        g_xn[((long long)b * HWW + l) * CC + c] = v * lng[c] + lnb[c];
    }
}

// ------------- causal depthwise conv1d + silu, writes SCAN order --------------
__global__ void conv1d_k(const float* __restrict__ cw, const float* __restrict__ cb)
{
    int d = threadIdx.x;     // 512
    int t = blockIdx.x;      // scan index
    int b = blockIdx.y;
    int dir = blockIdx.z;
    float w0 = cw[d * 4 + 0], w1 = cw[d * 4 + 1], w2 = cw[d * 4 + 2], w3 = cw[d * 4 + 3];
    float s = cb[d];
    long long bb = (long long)b * LL;
    if (t >= 3) s += g_xz[(bb + seq_map(dir, t - 3)) * 1024 + d] * w0;
    if (t >= 2) s += g_xz[(bb + seq_map(dir, t - 2)) * 1024 + d] * w1;
    if (t >= 1) s += g_xz[(bb + seq_map(dir, t - 1)) * 1024 + d] * w2;
    s += g_xz[(bb + seq_map(dir, t)) * 1024 + d] * w3;
    g_xm[(((long long)dir * BB + b) * LL + t) * DI + d] = silu_f(s);
}

// ------------------------- dt = softplus(proj[:,:16] @ dt_w.T + dt_b) --------
__global__ void dt_k(const float* __restrict__ dtw, const float* __restrict__ dtbias)
{
    __shared__ float pr[16];
    int d = threadIdx.x;
    int t = blockIdx.x, b = blockIdx.y, dir = blockIdx.z;
    long long row = ((long long)dir * BB + b) * LL + t;
    if (d < 16) pr[d] = g_projm[row * 48 + d];
    __syncthreads();
    float acc = dtbias[d];
#pragma unroll
    for (int r = 0; r < 16; r++) acc += pr[r] * dtw[d * 16 + r];
    float dt = (acc > 15.f) ? acc : log1pf(expf(acc));
    g_dtb[row * DI + d] = dt;
}

// ------------------------- selective scan (linear addressing) -----------------
// warp = 2 channels x 16 states; stores y ungated at scan index t.
__global__ void __launch_bounds__(128) scan_k(const float* __restrict__ A_log,
                                              const float* __restrict__ Dp)
{
    int tid = threadIdx.x;
    int lane = tid & 31;
    int gwarp = blockIdx.x * 4 + (tid >> 5);          // 0..2047
    int dir = gwarp >> 9;
    int b = (gwarp >> 8) & 1;
    int d = ((gwarp & 255) << 1) | (lane >> 4);
    int s = lane & 15;

    float Av = -expf(A_log[d * 16 + s]);
    float Dv = Dp[d];
    long long dbase = ((long long)dir * BB + b) * LL;
    const float* pdt = g_dtb + dbase * DI + d;
    const float* pxm = g_xm + dbase * DI + d;
    const float* pB  = g_projm + dbase * 48 + 16 + s;
    const float* pC  = g_projm + dbase * 48 + 32 + s;
    float* py        = g_y + dbase * DI + d;

    const int PF = 4;
    float f_dt[PF], f_x[PF], f_B[PF], f_C[PF];
#pragma unroll
    for (int i = 0; i < PF; i++) {
        f_dt[i] = pdt[i * DI];
        f_x[i]  = pxm[i * DI];
        f_B[i]  = pB[i * 48];
        f_C[i]  = pC[i * 48];
    }
    const float* qdt = pdt + PF * DI;
    const float* qxm = pxm + PF * DI;
    const float* qB  = pB + PF * 48;
    const float* qC  = pC + PF * 48;

    float h = 0.f;
    for (int t0 = 0; t0 < LL; t0 += PF) {
        bool pf = (t0 + PF < LL);
#pragma unroll
        for (int i = 0; i < PF; i++) {
            float dtv = f_dt[i], xv = f_x[i], Bv = f_B[i], Cv = f_C[i];
            if (pf) {
                f_dt[i] = qdt[i * DI];
                f_x[i]  = qxm[i * DI];
                f_B[i]  = qB[i * 48];
                f_C[i]  = qC[i * 48];
            }
            float dA = __expf(dtv * Av);
            h = fmaf(dA, h, dtv * xv * Bv);
            float part = h * Cv;
            part += __shfl_xor_sync(0xffffffffu, part, 1);
            part += __shfl_xor_sync(0xffffffffu, part, 2);
            part += __shfl_xor_sync(0xffffffffu, part, 4);
            part += __shfl_xor_sync(0xffffffffu, part, 8);
            if (s == 0) py[i * DI] = fmaf(Dv, xv, part);
        }
        qdt += PF * DI; qxm += PF * DI; qB += PF * 48; qC += PF * 48; py += PF * DI;
    }
}

// ----- gather 4 directions back to natural order, apply silu(z) gate ----------
__global__ void ysum_k()
{
    long long i = (long long)blockIdx.x * blockDim.x + threadIdx.x;
    if (i >= (long long)BL * DI) return;
    int d = (int)(i & (DI - 1));
    int l = (int)((i / DI) % LL);
    int b = (int)(i / ((long long)LL * DI));
    int t2 = (l % WW) * HH + l / WW;   // transpose involution (H==W==48)
    const long long st = (long long)BB * LL * DI;
    long long bb = (long long)b * LL * DI;
    float y = g_y[bb + (long long)l * DI + d]
            + g_y[st + bb + (long long)(LL - 1 - l) * DI + d]
            + g_y[2 * st + bb + (long long)t2 * DI + d]
            + g_y[3 * st + bb + (long long)(LL - 1 - t2) * DI + d];
    float z = g_xz[((long long)b * LL + l) * 1024 + DI + d];
    g_ysum[((long long)b * LL + l) * DI + d] = y * silu_f(z);
}

// ------------------------- SE head --------------------------------------------
__global__ void mean_k()
{
    int c = blockIdx.x, b = blockIdx.y;
    long long base = ((long long)b * CC + c) * HWW;
    float s = 0.f;
    for (int l = threadIdx.x; l < HWW; l += 256)
        s += g_featloc[base + l] + g_featglob[base + l];
    __shared__ float red[256];
    red[threadIdx.x] = s;
    __syncthreads();
    for (int o = 128; o; o >>= 1) {
        if (threadIdx.x < o) red[threadIdx.x] += red[threadIdx.x + o];
        __syncthreads();
    }
    if (threadIdx.x == 0) g_sv[b * CC + c] = red[0] / (float)HWW;
}

__global__ void fc_k(const float* __restrict__ fc1, const float* __restrict__ fc2)
{
    int b = blockIdx.x;
    __shared__ float ss[CC], tt[16];
    int tid = threadIdx.x;   // 256
    ss[tid] = g_sv[b * CC + tid];
    __syncthreads();
    if (tid < 16) {
        float a = 0.f;
        for (int c = 0; c < CC; c++) a += ss[c] * fc1[tid * CC + c];
        tt[tid] = fmaxf(a, 0.f);
    }
    __syncthreads();
    float z0 = 0.f, z1 = 0.f;
#pragma unroll
    for (int m = 0; m < 16; m++) {
        z0 += tt[m] * fc2[tid * 16 + m];
        z1 += tt[m] * fc2[(CC + tid) * 16 + m];
    }
    float mx = fmaxf(z0, z1);
    float e0 = expf(z0 - mx), e1 = expf(z1 - mx);
    float w0 = e0 / (e0 + e1);
    g_wv[b * 2 * CC + tid] = w0;
    g_wv[b * 2 * CC + CC + tid] = 1.f - w0;
}

__global__ void final_k(float* __restrict__ out)
{
    long long i = (long long)blockIdx.x * 256 + threadIdx.x;
    if (i >= (long long)BB * CC * HWW) return;
    int c = (int)((i / HWW) % CC);
    int b = (int)(i / ((long long)CC * HWW));
    out[i] = g_wv[b * 2 * CC + c] * g_featloc[i] + g_wv[b * 2 * CC + CC + c] * g_featglob[i];
}

// ------------------------- launch ---------------------------------------------
extern "C" void kernel_launch(void* const* d_in, const int* in_sizes, int n_in,
                              void* d_out, int out_size)
{
    const float* x        = (const float*)d_in[0];
    const float* reduce_w = (const float*)d_in[1];
    const float* bn0_g    = (const float*)d_in[2];
    const float* bn0_b    = (const float*)d_in[3];
    const float* proj_w   = (const float*)d_in[4];
    const float* bn1_g    = (const float*)d_in[5];
    const float* bn1_b    = (const float*)d_in[6];
    const float* dwh_w    = (const float*)d_in[7];
    const float* bnh_g    = (const float*)d_in[8];
    const float* bnh_b    = (const float*)d_in[9];
    const float* dwv_w    = (const float*)d_in[10];
    const float* bnv_g    = (const float*)d_in[11];
    const float* bnv_b    = (const float*)d_in[12];
    const float* fus_w    = (const float*)d_in[13];
    const float* fus_b    = (const float*)d_in[14];
    const float* ln_g     = (const float*)d_in[15];
    const float* ln_b     = (const float*)d_in[16];
    const float* in_w     = (const float*)d_in[17];
    const float* conv_w   = (const float*)d_in[18];
    const float* conv_b   = (const float*)d_in[19];
    const float* xproj_w  = (const float*)d_in[20];
    const float* dt_w     = (const float*)d_in[21];
    const float* dt_b     = (const float*)d_in[22];
    const float* A_log    = (const float*)d_in[23];
    const float* Dp       = (const float*)d_in[24];
    const float* out_w    = (const float*)d_in[25];
    const float* fc1_w    = (const float*)d_in[26];
    const float* fc2_w    = (const float*)d_in[27];

    float *xred, *p, *hv, *featloc, *featglob, *xn, *xz, *xm, *projm, *ysum;
    cudaGetSymbolAddress((void**)&xred, g_xred);
    cudaGetSymbolAddress((void**)&p, g_p);
    cudaGetSymbolAddress((void**)&hv, g_hv);
    cudaGetSymbolAddress((void**)&featloc, g_featloc);
    cudaGetSymbolAddress((void**)&featglob, g_featglob);
    cudaGetSymbolAddress((void**)&xn, g_xn);
    cudaGetSymbolAddress((void**)&xz, g_xz);
    cudaGetSymbolAddress((void**)&xm, g_xm);
    cudaGetSymbolAddress((void**)&projm, g_projm);
    cudaGetSymbolAddress((void**)&ysum, g_ysum);

    // 1) x = relu(bn0(reduce_w @ xin))
    gemm128<1, false><<<dim3(36, 2, BB), 256>>>(reduce_w, x, xred, 256, 2304, 512,
        0, (long long)CIN * HWW, (long long)CC * HWW, bn0_g, bn0_b, (const float*)0, 0);
    // 2) p = relu(bn1(proj_w @ x))
    gemm128<1, false><<<dim3(36, 2, BB), 256>>>(proj_w, xred, p, 256, 2304, 256,
        0, (long long)CC * HWW, (long long)CC * HWW, bn1_g, bn1_b, (const float*)0, 0);
    // 3) depthwise h+v fused
    dwconv_k<<<(BB * CC * HWW + 255) / 256, 256>>>(p, dwh_w, dwv_w,
                                                   bnh_g, bnh_b, bnv_g, bnv_b, hv);
    // 4) feat_local = fus_w @ (h+v) + fus_b
    gemm128<2, false><<<dim3(36, 2, BB), 256>>>(fus_w, hv, featloc, 256, 2304, 256,
        0, (long long)CC * HWW, (long long)CC * HWW, (const float*)0, fus_b, (const float*)0, 0);
    // 5) layernorm over C (shared by all directions)
    ln_stats_k<<<dim3((HWW + 255) / 256, BB), 256>>>(xred);
    trans_norm_k<<<dim3(HWW / 32, CC / 32, BB), dim3(32, 8)>>>(xred, ln_g, ln_b);
    // 6) in_proj: xz = xn @ in_w.T
    gemm128<0, true><<<dim3(16, 18, BB), 256>>>(xn, in_w, xz, 2304, 1024, 256,
        (long long)LL * CC, 0, (long long)LL * 1024, (const float*)0, (const float*)0,
        (const float*)0, 0);
    // 7) causal conv1d + silu -> scan-ordered xm
    conv1d_k<<<dim3(LL, BB, 4), 512>>>(conv_w, conv_b);
    // 8) xproj per direction: proj = xm @ xproj_w.T
    gemm128<0, true><<<dim3(1, 18, 8), 256>>>(xm, xproj_w, projm, 2304, 48, 512,
        (long long)LL * DI, 0, (long long)LL * 48, (const float*)0, (const float*)0,
        (const float*)0, 0);
    // 9) dt = softplus(...)
    dt_k<<<dim3(LL, BB, 4), 512>>>(dt_w, dt_b);
    // 10) selective scan
    scan_k<<<512, 128>>>(A_log, Dp);
    // 11) gather directions to natural order + silu(z) gate
    ysum_k<<<(BL * DI + 255) / 256, 256>>>();
    // 12) feat_global = 0.25 * (out_w @ ysum) + x
    gemm128<3, true><<<dim3(36, 2, BB), 256>>>(out_w, ysum, featglob, 256, 2304, 512,
        0, (long long)LL * DI, (long long)CC * HWW, (const float*)0, (const float*)0,
        xred, (long long)CC * HWW);
    // 13) SE head + final combine
    mean_k<<<dim3(CC, BB), 256>>>();
    fc_k<<<BB, 256>>>(fc1_w, fc2_w);
    final_k<<<(BB * CC * HWW + 255) / 256, 256>>>((float*)d_out);
}

// round 4
// speedup vs baseline: 2.3182x; 1.4353x over previous
#include <cuda_runtime.h>
#include <math.h>

#define BB  2
#define CIN 512
#define CC  256
#define HH  48
#define WW  48
#define HWW 2304
#define LL  2304
#define DI  512
#define BL  (BB*LL)
#define BNF 0.9999950000374997f   /* 1/sqrt(1+1e-5) */

// ------------------------- static scratch (no allocs) -------------------------
__device__ __align__(256) float g_xred[BB*CC*HWW];
__device__ __align__(256) float g_p[BB*CC*HWW];
__device__ __align__(256) float g_hv[BB*CC*HWW];
__device__ __align__(256) float g_featloc[BB*CC*HWW];
__device__ __align__(256) float g_featglob[BB*CC*HWW];
__device__ __align__(256) float g_mu[BB*HWW];
__device__ __align__(256) float g_rstd[BB*HWW];
__device__ __align__(256) float g_xn[BL*CC];          // (b,l,c)
__device__ __align__(256) float g_xz[BL*2*DI];        // (b,l,1024): xm0 | z
__device__ __align__(256) float g_xm[4*BL*DI];        // (dir,b,t,d) SCAN order
__device__ __align__(256) float g_projm[4*BL*48];     // (dir,b,t,48) SCAN order
__device__ __align__(256) float g_dtb[4*BL*DI];       // SCAN order
__device__ __align__(256) float g_y[4*BL*DI];         // SCAN order, ungated
__device__ __align__(256) float g_ysum[BL*DI];        // natural order, gated
__device__ __align__(256) float g_dtwT[16*DI];        // transposed dt_w
__device__ __align__(256) float g_sv[BB*CC];
__device__ __align__(256) float g_wv[BB*2*CC];

__device__ __forceinline__ int seq_map(int dir, int t) {
    if (dir == 0) return t;
    if (dir == 1) return LL - 1 - t;
    int u = (dir == 2) ? t : (LL - 1 - t);
    int h = u % HH, w = u / HH;
    return h * WW + w;
}

__device__ __forceinline__ float silu_f(float x) { return x / (1.f + __expf(-x)); }

// ------------------------- 128x64 SGEMM, k-tile 32 ----------------------------
// C[m,n] = f(sum_k A[m,k] * B[k,n])   (TB=false: B is KxN rowmajor)
// C[m,n] = f(sum_k A[m,k] * B[n,k])   (TB=true:  B is NxK rowmajor)
// Requires M%128==0, K%32==0. N%64==0 unless TB (then guarded).
template<int MODE, bool TB>
__global__ void __launch_bounds__(256) gemm128(
    const float* __restrict__ A, const float* __restrict__ B, float* __restrict__ C,
    int M, int N, int K,
    long long sA, long long sB, long long sC,
    const float* __restrict__ scale, const float* __restrict__ bias,
    const float* __restrict__ extra, long long sE)
{
    __shared__ float As[32][132];
    __shared__ float Bs[32][68];
    const float* Ab = A + (long long)blockIdx.z * sA;
    const float* Bb = B + (long long)blockIdx.z * sB;
    float* Cb = C + (long long)blockIdx.z * sC;
    int tid = threadIdx.x;
    int m0 = blockIdx.y * 128, n0 = blockIdx.x * 64;
    int tx = tid & 15, ty = tid >> 4;

    // A tile 128x32: rows (tid>>3)+32i, k (tid&7)*4  -> full 128B rows per 8 lanes
    int arow = tid >> 3;
    int akk = (tid & 7) * 4;
    const float* aptr = Ab + (long long)(m0 + arow) * K + akk;
    const long long astep = (long long)32 * K;

    int bk, bn;
    const float* bptr;
    bool bv0 = true, bv1 = true;
    if (TB) {   // B tile 64(n) x 32(k): rows (tid>>3)+32i, k (tid&7)*4
        bn = tid >> 3;
        bk = (tid & 7) * 4;
        bv0 = (n0 + bn) < N;
        bv1 = (n0 + bn + 32) < N;
        bptr = Bb + (long long)(n0 + bn) * K + bk;
    } else {    // B tile 32(k) x 64(n): k rows (tid>>4)*2 {+0,+1}, n (tid&15)*4
        bk = (tid >> 4) * 2;
        bn = (tid & 15) * 4;
        bptr = Bb + (long long)bk * N + n0 + bn;
    }

    float4 pa[4], pb[2];
#pragma unroll
    for (int i = 0; i < 4; i++) pa[i] = *(const float4*)(aptr + i * astep);
    if (TB) {
        pb[0] = bv0 ? *(const float4*)(bptr) : make_float4(0.f,0.f,0.f,0.f);
        pb[1] = bv1 ? *(const float4*)(bptr + astep) : make_float4(0.f,0.f,0.f,0.f);
    } else {
        pb[0] = *(const float4*)(bptr);
        pb[1] = *(const float4*)(bptr + N);
    }

    float acc[8][4] = {};

    for (int k0 = 0; k0 < K; k0 += 32) {
#pragma unroll
        for (int i = 0; i < 4; i++) {
            As[akk+0][arow+32*i] = pa[i].x;
            As[akk+1][arow+32*i] = pa[i].y;
            As[akk+2][arow+32*i] = pa[i].z;
            As[akk+3][arow+32*i] = pa[i].w;
        }
        if (TB) {
            Bs[bk+0][bn] = pb[0].x; Bs[bk+1][bn] = pb[0].y;
            Bs[bk+2][bn] = pb[0].z; Bs[bk+3][bn] = pb[0].w;
            Bs[bk+0][bn+32] = pb[1].x; Bs[bk+1][bn+32] = pb[1].y;
            Bs[bk+2][bn+32] = pb[1].z; Bs[bk+3][bn+32] = pb[1].w;
        } else {
            *(float4*)&Bs[bk][bn] = pb[0];
            *(float4*)&Bs[bk+1][bn] = pb[1];
        }
        __syncthreads();
        if (k0 + 32 < K) {
            aptr += 32;
#pragma unroll
            for (int i = 0; i < 4; i++) pa[i] = *(const float4*)(aptr + i * astep);
            if (TB) {
                bptr += 32;
                pb[0] = bv0 ? *(const float4*)(bptr) : make_float4(0.f,0.f,0.f,0.f);
                pb[1] = bv1 ? *(const float4*)(bptr + astep) : make_float4(0.f,0.f,0.f,0.f);
            } else {
                bptr += (long long)32 * N;
                pb[0] = *(const float4*)(bptr);
                pb[1] = *(const float4*)(bptr + N);
            }
        }
#pragma unroll 8
        for (int k = 0; k < 32; k++) {
            float4 a0 = *(const float4*)&As[k][ty*8];
            float4 a1 = *(const float4*)&As[k][ty*8+4];
            float4 b4 = *(const float4*)&Bs[k][tx*4];
            float a[8] = {a0.x,a0.y,a0.z,a0.w,a1.x,a1.y,a1.z,a1.w};
            float bbv[4] = {b4.x,b4.y,b4.z,b4.w};
#pragma unroll
            for (int i = 0; i < 8; i++)
#pragma unroll
                for (int j = 0; j < 4; j++)
                    acc[i][j] = fmaf(a[i], bbv[j], acc[i][j]);
        }
        __syncthreads();
    }

#pragma unroll
    for (int i = 0; i < 8; i++) {
        int m = m0 + ty*8 + i;
        float sc = 1.f, bi = 0.f;
        if (MODE == 1) { sc = scale[m] * BNF; bi = bias[m]; }
        if (MODE == 2) { bi = bias[m]; }
        int n = n0 + tx*4;
        if (!TB || n + 3 < N) {
            float v[4];
#pragma unroll
            for (int j = 0; j < 4; j++) {
                float t = acc[i][j];
                if (MODE == 1) t = fmaxf(fmaf(t, sc, bi), 0.f);
                else if (MODE == 2) t = t + bi;
                else if (MODE == 3)
                    t = t * 0.25f + extra[(long long)blockIdx.z * sE + (long long)m * N + n + j];
                v[j] = t;
            }
            float4 o = make_float4(v[0], v[1], v[2], v[3]);
            *(float4*)(Cb + (long long)m * N + n) = o;
        }
    }
}

// ------------------------- depthwise 1x7 + 7x1 fused --------------------------
__global__ void dwconv_k(const float* __restrict__ p,
                         const float* __restrict__ wh, const float* __restrict__ wv,
                         const float* __restrict__ hg, const float* __restrict__ hb,
                         const float* __restrict__ vg, const float* __restrict__ vb,
                         float* __restrict__ out)
{
    int idx = blockIdx.x * blockDim.x + threadIdx.x;
    if (idx >= BB * CC * HWW) return;
    int l = idx % HWW;
    int c = (idx / HWW) % CC;
    int y = l / WW, x = l % WW;
    const float* base = p + (idx - l);
    float sh = 0.f, sv = 0.f;
#pragma unroll
    for (int j = 0; j < 7; j++) {
        int xx = x - 3 + j;
        if (xx >= 0 && xx < WW) sh += base[y * WW + xx] * wh[c * 7 + j];
        int yy = y - 3 + j;
        if (yy >= 0 && yy < HH) sv += base[yy * WW + x] * wv[c * 7 + j];
    }
    float rh = fmaxf(sh * (hg[c] * BNF) + hb[c], 0.f);
    float rv = fmaxf(sv * (vg[c] * BNF) + vb[c], 0.f);
    out[idx] = rh + rv;
}

// ------------------------- layernorm over C -----------------------------------
__global__ void ln_stats_k(const float* __restrict__ x)
{
    int l = blockIdx.x * blockDim.x + threadIdx.x;
    int b = blockIdx.y;
    if (l >= HWW) return;
    const float* xp = x + (long long)b * CC * HWW + l;
    float s = 0.f, ss = 0.f;
#pragma unroll 8
    for (int c = 0; c < CC; c++) { float v = xp[(long long)c * HWW]; s += v; ss += v * v; }
    float mu = s * (1.f / CC);
    float var = ss * (1.f / CC) - mu * mu;
    g_mu[b * HWW + l] = mu;
    g_rstd[b * HWW + l] = rsqrtf(var + 1e-5f);
}

__global__ void trans_norm_k(const float* __restrict__ x,
                             const float* __restrict__ lng, const float* __restrict__ lnb)
{
    __shared__ float tile[32][33];
    int b = blockIdx.z;
    int l0 = blockIdx.x * 32, c0 = blockIdx.y * 32;
    int tx = threadIdx.x, ty = threadIdx.y;   // (32,8)
#pragma unroll
    for (int i = 0; i < 4; i++) {
        int c = c0 + ty + i * 8;
        tile[ty + i * 8][tx] = x[((long long)b * CC + c) * HWW + l0 + tx];
    }
    __syncthreads();
#pragma unroll
    for (int i = 0; i < 4; i++) {
        int l = l0 + ty + i * 8;
        int c = c0 + tx;
        float v = (tile[tx][ty + i * 8] - g_mu[b * HWW + l]) * g_rstd[b * HWW + l];
        g_xn[((long long)b * HWW + l) * CC + c] = v * lng[c] + lnb[c];
    }
}

// -------- causal depthwise conv1d + silu, chunked rolling window ---------------
#define CCT 64
__global__ void __launch_bounds__(512) conv1d_k(const float* __restrict__ cw,
                                                const float* __restrict__ cb)
{
    int d = threadIdx.x;     // 512
    int t0 = blockIdx.x * CCT;
    int b = blockIdx.y;
    int dir = blockIdx.z;
    float w0 = cw[d * 4 + 0], w1 = cw[d * 4 + 1], w2 = cw[d * 4 + 2], w3 = cw[d * 4 + 3];
    float bias = cb[d];
    long long bb = (long long)b * LL;
    float x0 = (t0 >= 3) ? g_xz[(bb + seq_map(dir, t0 - 3)) * 1024 + d] : 0.f;
    float x1 = (t0 >= 2) ? g_xz[(bb + seq_map(dir, t0 - 2)) * 1024 + d] : 0.f;
    float x2 = (t0 >= 1) ? g_xz[(bb + seq_map(dir, t0 - 1)) * 1024 + d] : 0.f;
    float xn = g_xz[(bb + seq_map(dir, t0)) * 1024 + d];
    float* yo = &g_xm[(((long long)dir * BB + b) * LL + t0) * DI + d];
    for (int i = 0; i < CCT; i++) {
        float xnn = (i + 1 < CCT) ? g_xz[(bb + seq_map(dir, t0 + i + 1)) * 1024 + d] : 0.f;
        float s = bias + w0 * x0 + w1 * x1 + w2 * x2 + w3 * xn;
        yo[(long long)i * DI] = silu_f(s);
        x0 = x1; x1 = x2; x2 = xn; xn = xnn;
    }
}

// ------------------------- transpose dt_w once --------------------------------
__global__ void dtwt_k(const float* __restrict__ dtw)
{
    int i = blockIdx.x * 256 + threadIdx.x;   // 8192
    int dd = i >> 4, r = i & 15;
    g_dtwT[r * DI + dd] = dtw[i];
}

// ---------- dt = softplus(proj[:,:16] @ dt_w.T + dt_b), 16 t per block --------
#define DTT 16
__global__ void __launch_bounds__(512) dt_k(const float* __restrict__ dtbias)
{
    __shared__ float pr[DTT][16];
    int d = threadIdx.x;
    int t0 = blockIdx.x * DTT;
    int b = blockIdx.y, dir = blockIdx.z;
    long long row0 = ((long long)dir * BB + b) * LL + t0;
    if (d < DTT * 16) {
        int ti = d >> 4, r = d & 15;
        pr[ti][r] = g_projm[(row0 + ti) * 48 + r];
    }
    float wreg[16];
#pragma unroll
    for (int r = 0; r < 16; r++) wreg[r] = g_dtwT[r * DI + d];
    float bias = dtbias[d];
    __syncthreads();
    float* out = &g_dtb[row0 * DI + d];
#pragma unroll 4
    for (int t = 0; t < DTT; t++) {
        float acc = bias;
#pragma unroll
        for (int r = 0; r < 16; r++) acc = fmaf(pr[t][r], wreg[r], acc);
        float dt = (acc > 15.f) ? acc : log1pf(expf(acc));
        out[(long long)t * DI] = dt;
    }
}

// ------------------------- selective scan (linear addressing) -----------------
// warp = 2 channels x 16 states; stores y ungated at scan index t.
__global__ void __launch_bounds__(128) scan_k(const float* __restrict__ A_log,
                                              const float* __restrict__ Dp)
{
    int tid = threadIdx.x;
    int lane = tid & 31;
    int gwarp = blockIdx.x * 4 + (tid >> 5);          // 0..2047
    int dir = gwarp >> 9;
    int b = (gwarp >> 8) & 1;
    int d = ((gwarp & 255) << 1) | (lane >> 4);
    int s = lane & 15;

    float Av = -expf(A_log[d * 16 + s]);
    float Dv = Dp[d];
    long long dbase = ((long long)dir * BB + b) * LL;
    const float* pdt = g_dtb + dbase * DI + d;
    const float* pxm = g_xm + dbase * DI + d;
    const float* pB  = g_projm + dbase * 48 + 16 + s;
    const float* pC  = g_projm + dbase * 48 + 32 + s;
    float* py        = g_y + dbase * DI + d;

    const int PF = 4;
    float f_dt[PF], f_x[PF], f_B[PF], f_C[PF];
#pragma unroll
    for (int i = 0; i < PF; i++) {
        f_dt[i] = pdt[i * DI];
        f_x[i]  = pxm[i * DI];
        f_B[i]  = pB[i * 48];
        f_C[i]  = pC[i * 48];
    }
    const float* qdt = pdt + PF * DI;
    const float* qxm = pxm + PF * DI;
    const float* qB  = pB + PF * 48;
    const float* qC  = pC + PF * 48;

    float h = 0.f;
    for (int t0 = 0; t0 < LL; t0 += PF) {
        bool pf = (t0 + PF < LL);
#pragma unroll
        for (int i = 0; i < PF; i++) {
            float dtv = f_dt[i], xv = f_x[i], Bv = f_B[i], Cv = f_C[i];
            if (pf) {
                f_dt[i] = qdt[i * DI];
                f_x[i]  = qxm[i * DI];
                f_B[i]  = qB[i * 48];
                f_C[i]  = qC[i * 48];
            }
            float dA = __expf(dtv * Av);
            h = fmaf(dA, h, dtv * xv * Bv);
            float part = h * Cv;
            part += __shfl_xor_sync(0xffffffffu, part, 1);
            part += __shfl_xor_sync(0xffffffffu, part, 2);
            part += __shfl_xor_sync(0xffffffffu, part, 4);
            part += __shfl_xor_sync(0xffffffffu, part, 8);
            if (s == 0) py[i * DI] = fmaf(Dv, xv, part);
        }
        qdt += PF * DI; qxm += PF * DI; qB += PF * 48; qC += PF * 48; py += PF * DI;
    }
}

// ----- gather 4 directions back to natural order, apply silu(z) gate ----------
__global__ void ysum_k()
{
    long long i = (long long)blockIdx.x * blockDim.x + threadIdx.x;
    if (i >= (long long)BL * DI) return;
    int d = (int)(i & (DI - 1));
    int l = (int)((i / DI) % LL);
    int b = (int)(i / ((long long)LL * DI));
    int t2 = (l % WW) * HH + l / WW;   // transpose involution (H==W==48)
    const long long st = (long long)BB * LL * DI;
    long long bb = (long long)b * LL * DI;
    float y = g_y[bb + (long long)l * DI + d]
            + g_y[st + bb + (long long)(LL - 1 - l) * DI + d]
            + g_y[2 * st + bb + (long long)t2 * DI + d]
            + g_y[3 * st + bb + (long long)(LL - 1 - t2) * DI + d];
    float z = g_xz[((long long)b * LL + l) * 1024 + DI + d];
    g_ysum[((long long)b * LL + l) * DI + d] = y * silu_f(z);
}

// ------------------------- SE head --------------------------------------------
__global__ void mean_k()
{
    int c = blockIdx.x, b = blockIdx.y;
    long long base = ((long long)b * CC + c) * HWW;
    float s = 0.f;
    for (int l = threadIdx.x; l < HWW; l += 256)
        s += g_featloc[base + l] + g_featglob[base + l];
    __shared__ float red[256];
    red[threadIdx.x] = s;
    __syncthreads();
    for (int o = 128; o; o >>= 1) {
        if (threadIdx.x < o) red[threadIdx.x] += red[threadIdx.x + o];
        __syncthreads();
    }
    if (threadIdx.x == 0) g_sv[b * CC + c] = red[0] / (float)HWW;
}

__global__ void fc_k(const float* __restrict__ fc1, const float* __restrict__ fc2)
{
    int b = blockIdx.x;
    __shared__ float ss[CC], tt[16];
    int tid = threadIdx.x;   // 256
    ss[tid] = g_sv[b * CC + tid];
    __syncthreads();
    if (tid < 16) {
        float a = 0.f;
        for (int c = 0; c < CC; c++) a += ss[c] * fc1[tid * CC + c];
        tt[tid] = fmaxf(a, 0.f);
    }
    __syncthreads();
    float z0 = 0.f, z1 = 0.f;
#pragma unroll
    for (int m = 0; m < 16; m++) {
        z0 += tt[m] * fc2[tid * 16 + m];
        z1 += tt[m] * fc2[(CC + tid) * 16 + m];
    }
    float mx = fmaxf(z0, z1);
    float e0 = expf(z0 - mx), e1 = expf(z1 - mx);
    float w0 = e0 / (e0 + e1);
    g_wv[b * 2 * CC + tid] = w0;
    g_wv[b * 2 * CC + CC + tid] = 1.f - w0;
}

__global__ void final_k(float* __restrict__ out)
{
    long long i = (long long)blockIdx.x * 256 + threadIdx.x;
    if (i >= (long long)BB * CC * HWW) return;
    int c = (int)((i / HWW) % CC);
    int b = (int)(i / ((long long)CC * HWW));
    out[i] = g_wv[b * 2 * CC + c] * g_featloc[i] + g_wv[b * 2 * CC + CC + c] * g_featglob[i];
}

// ------------------------- launch ---------------------------------------------
extern "C" void kernel_launch(void* const* d_in, const int* in_sizes, int n_in,
                              void* d_out, int out_size)
{
    const float* x        = (const float*)d_in[0];
    const float* reduce_w = (const float*)d_in[1];
    const float* bn0_g    = (const float*)d_in[2];
    const float* bn0_b    = (const float*)d_in[3];
    const float* proj_w   = (const float*)d_in[4];
    const float* bn1_g    = (const float*)d_in[5];
    const float* bn1_b    = (const float*)d_in[6];
    const float* dwh_w    = (const float*)d_in[7];
    const float* bnh_g    = (const float*)d_in[8];
    const float* bnh_b    = (const float*)d_in[9];
    const float* dwv_w    = (const float*)d_in[10];
    const float* bnv_g    = (const float*)d_in[11];
    const float* bnv_b    = (const float*)d_in[12];
    const float* fus_w    = (const float*)d_in[13];
    const float* fus_b    = (const float*)d_in[14];
    const float* ln_g     = (const float*)d_in[15];
    const float* ln_b     = (const float*)d_in[16];
    const float* in_w     = (const float*)d_in[17];
    const float* conv_w   = (const float*)d_in[18];
    const float* conv_b   = (const float*)d_in[19];
    const float* xproj_w  = (const float*)d_in[20];
    const float* dt_w     = (const float*)d_in[21];
    const float* dt_b     = (const float*)d_in[22];
    const float* A_log    = (const float*)d_in[23];
    const float* Dp       = (const float*)d_in[24];
    const float* out_w    = (const float*)d_in[25];
    const float* fc1_w    = (const float*)d_in[26];
    const float* fc2_w    = (const float*)d_in[27];

    float *xred, *p, *hv, *featloc, *featglob, *xn, *xz, *xm, *projm, *ysum;
    cudaGetSymbolAddress((void**)&xred, g_xred);
    cudaGetSymbolAddress((void**)&p, g_p);
    cudaGetSymbolAddress((void**)&hv, g_hv);
    cudaGetSymbolAddress((void**)&featloc, g_featloc);
    cudaGetSymbolAddress((void**)&featglob, g_featglob);
    cudaGetSymbolAddress((void**)&xn, g_xn);
    cudaGetSymbolAddress((void**)&xz, g_xz);
    cudaGetSymbolAddress((void**)&xm, g_xm);
    cudaGetSymbolAddress((void**)&projm, g_projm);
    cudaGetSymbolAddress((void**)&ysum, g_ysum);

    // 1) x = relu(bn0(reduce_w @ xin))
    gemm128<1, false><<<dim3(36, 2, BB), 256>>>(reduce_w, x, xred, 256, 2304, 512,
        0, (long long)CIN * HWW, (long long)CC * HWW, bn0_g, bn0_b, (const float*)0, 0);
    // 2,3) layernorm over C (shared by all directions)
    ln_stats_k<<<dim3((HWW + 255) / 256, BB), 256>>>(xred);
    trans_norm_k<<<dim3(HWW / 32, CC / 32, BB), dim3(32, 8)>>>(xred, ln_g, ln_b);
    // 4) in_proj: xz = xn @ in_w.T     <-- profiled slot
    gemm128<0, true><<<dim3(16, 18, BB), 256>>>(xn, in_w, xz, 2304, 1024, 256,
        (long long)LL * CC, 0, (long long)LL * 1024, (const float*)0, (const float*)0,
        (const float*)0, 0);
    // 5) transpose dt_w once
    dtwt_k<<<32, 256>>>(dt_w);
    // 6) causal conv1d + silu -> scan-ordered xm (chunked)
    conv1d_k<<<dim3(LL / CCT, BB, 4), 512>>>(conv_w, conv_b);
    // 7) xproj per direction: proj = xm @ xproj_w.T
    gemm128<0, true><<<dim3(1, 18, 8), 256>>>(xm, xproj_w, projm, 2304, 48, 512,
        (long long)LL * DI, 0, (long long)LL * 48, (const float*)0, (const float*)0,
        (const float*)0, 0);
    // 8) dt = softplus(...)
    dt_k<<<dim3(LL / DTT, BB, 4), 512>>>(dt_b);
    // 9) selective scan
    scan_k<<<512, 128>>>(A_log, Dp);
    // 10) gather directions to natural order + silu(z) gate
    ysum_k<<<(BL * DI + 255) / 256, 256>>>();
    // 11) feat_global = 0.25 * (out_w @ ysum) + x
    gemm128<3, true><<<dim3(36, 2, BB), 256>>>(out_w, ysum, featglob, 256, 2304, 512,
        0, (long long)LL * DI, (long long)CC * HWW, (const float*)0, (const float*)0,
        xred, (long long)CC * HWW);
    // 12) p = relu(bn1(proj_w @ x))   (local branch)
    gemm128<1, false><<<dim3(36, 2, BB), 256>>>(proj_w, xred, p, 256, 2304, 256,
        0, (long long)CC * HWW, (long long)CC * HWW, bn1_g, bn1_b, (const float*)0, 0);
    // 13) depthwise h+v fused
    dwconv_k<<<(BB * CC * HWW + 255) / 256, 256>>>(p, dwh_w, dwv_w,
                                                   bnh_g, bnh_b, bnv_g, bnv_b, hv);
    // 14) feat_local = fus_w @ (h+v) + fus_b
    gemm128<2, false><<<dim3(36, 2, BB), 256>>>(fus_w, hv, featloc, 256, 2304, 256,
        0, (long long)CC * HWW, (long long)CC * HWW, (const float*)0, fus_b, (const float*)0, 0);
    // 15-17) SE head + final combine
    mean_k<<<dim3(CC, BB), 256>>>();
    fc_k<<<BB, 256>>>(fc1_w, fc2_w);
    final_k<<<(BB * CC * HWW + 255) / 256, 256>>>((float*)d_out);
}

// round 5
// speedup vs baseline: 2.8531x; 1.2307x over previous
#include <cuda_runtime.h>
#include <cuda_bf16.h>
#include <math.h>

#define BB  2
#define CIN 512
#define CC  256
#define HH  48
#define WW  48
#define HWW 2304
#define LL  2304
#define DI  512
#define BL  (BB*LL)
#define BNF 0.9999950000374997f   /* 1/sqrt(1+1e-5) */

// ------------------------- static scratch (no allocs) -------------------------
__device__ __align__(256) float g_xred[BB*CC*HWW];
__device__ __align__(256) float g_p[BB*CC*HWW];
__device__ __align__(256) float g_hv[BB*CC*HWW];
__device__ __align__(256) float g_featloc[BB*CC*HWW];
__device__ __align__(256) float g_featglob[BB*CC*HWW];
__device__ __align__(256) float g_mu[BB*HWW];
__device__ __align__(256) float g_rstd[BB*HWW];
__device__ __align__(256) float g_xn[BL*CC];          // (b,l,c)
__device__ __align__(256) float g_xz[BL*2*DI];        // (b,l,1024): xm0 | z
__device__ __align__(256) float g_xm[4*BL*DI];        // (dir,b,t,d) SCAN order
__device__ __align__(256) float g_projm[4*BL*48];     // (dir,b,t,48) SCAN order
__device__ __align__(256) float g_dtb[4*BL*DI];       // SCAN order
__device__ __align__(256) __nv_bfloat16 g_y[4*BL*DI]; // SCAN order, ungated, bf16
__device__ __align__(256) float g_ysum[BL*DI];        // natural order, gated
__device__ __align__(256) float g_dtwT[16*DI];        // transposed dt_w
__device__ __align__(256) float g_sv[BB*CC];
__device__ __align__(256) float g_wv[BB*2*CC];

__device__ __forceinline__ int seq_map(int dir, int t) {
    if (dir == 0) return t;
    if (dir == 1) return LL - 1 - t;
    int u = (dir == 2) ? t : (LL - 1 - t);
    int h = u % HH, w = u / HH;
    return h * WW + w;
}

__device__ __forceinline__ float silu_f(float x) { return x / (1.f + __expf(-x)); }

// ---------------- 128x128 SGEMM, 8x8 microtile, NT (both K-contiguous) --------
// C[m,n] = sum_k A[m,k] * B[n,k].  Requires M%128==0, N%128==0, K%16==0.
__global__ void __launch_bounds__(256) gemm_nt_big(
    const float* __restrict__ A, const float* __restrict__ B, float* __restrict__ C,
    int M, int N, int K, long long sA, long long sC)
{
    __shared__ float As[16][132];
    __shared__ float Bs[16][132];
    int tid = threadIdx.x;
    int m0 = blockIdx.y * 128, n0 = blockIdx.x * 128;
    int r = tid >> 1;              // 0..127
    int kk = (tid & 1) * 8;        // 0 or 8
    const float* aptr = A + (long long)blockIdx.z * sA + (long long)(m0 + r) * K + kk;
    const float* bptr = B + (long long)(n0 + r) * K + kk;
    int tx = tid & 15, ty = tid >> 4;

    float4 pa0 = *(const float4*)(aptr);
    float4 pa1 = *(const float4*)(aptr + 4);
    float4 pb0 = *(const float4*)(bptr);
    float4 pb1 = *(const float4*)(bptr + 4);

    float acc[8][8] = {};

    for (int k0 = 0; k0 < K; k0 += 16) {
        As[kk+0][r]=pa0.x; As[kk+1][r]=pa0.y; As[kk+2][r]=pa0.z; As[kk+3][r]=pa0.w;
        As[kk+4][r]=pa1.x; As[kk+5][r]=pa1.y; As[kk+6][r]=pa1.z; As[kk+7][r]=pa1.w;
        Bs[kk+0][r]=pb0.x; Bs[kk+1][r]=pb0.y; Bs[kk+2][r]=pb0.z; Bs[kk+3][r]=pb0.w;
        Bs[kk+4][r]=pb1.x; Bs[kk+5][r]=pb1.y; Bs[kk+6][r]=pb1.z; Bs[kk+7][r]=pb1.w;
        __syncthreads();
        if (k0 + 16 < K) {
            aptr += 16; bptr += 16;
            pa0 = *(const float4*)(aptr);
            pa1 = *(const float4*)(aptr + 4);
            pb0 = *(const float4*)(bptr);
            pb1 = *(const float4*)(bptr + 4);
        }
#pragma unroll
        for (int k = 0; k < 16; k++) {
            float4 a0 = *(const float4*)&As[k][ty*8];
            float4 a1 = *(const float4*)&As[k][ty*8+4];
            float4 b0 = *(const float4*)&Bs[k][tx*8];
            float4 b1 = *(const float4*)&Bs[k][tx*8+4];
            float a[8] = {a0.x,a0.y,a0.z,a0.w,a1.x,a1.y,a1.z,a1.w};
            float b[8] = {b0.x,b0.y,b0.z,b0.w,b1.x,b1.y,b1.z,b1.w};
#pragma unroll
            for (int i = 0; i < 8; i++)
#pragma unroll
                for (int j = 0; j < 8; j++)
                    acc[i][j] = fmaf(a[i], b[j], acc[i][j]);
        }
        __syncthreads();
    }

    float* Cb = C + (long long)blockIdx.z * sC;
#pragma unroll
    for (int i = 0; i < 8; i++) {
        int m = m0 + ty*8 + i;
        float4 o0 = make_float4(acc[i][0], acc[i][1], acc[i][2], acc[i][3]);
        float4 o1 = make_float4(acc[i][4], acc[i][5], acc[i][6], acc[i][7]);
        *(float4*)(Cb + (long long)m * N + n0 + tx*8) = o0;
        *(float4*)(Cb + (long long)m * N + n0 + tx*8 + 4) = o1;
    }
}

// ------------------------- 128x64 SGEMM, k-tile 32 ----------------------------
// C[m,n] = f(sum_k A[m,k] * B[k,n])   (TB=false: B is KxN rowmajor)
// C[m,n] = f(sum_k A[m,k] * B[n,k])   (TB=true:  B is NxK rowmajor)
// Requires M%128==0, K%32==0. N%64==0 unless TB (then guarded).
template<int MODE, bool TB>
__global__ void __launch_bounds__(256) gemm128(
    const float* __restrict__ A, const float* __restrict__ B, float* __restrict__ C,
    int M, int N, int K,
    long long sA, long long sB, long long sC,
    const float* __restrict__ scale, const float* __restrict__ bias,
    const float* __restrict__ extra, long long sE)
{
    __shared__ float As[32][132];
    __shared__ float Bs[32][68];
    const float* Ab = A + (long long)blockIdx.z * sA;
    const float* Bb = B + (long long)blockIdx.z * sB;
    float* Cb = C + (long long)blockIdx.z * sC;
    int tid = threadIdx.x;
    int m0 = blockIdx.y * 128, n0 = blockIdx.x * 64;
    int tx = tid & 15, ty = tid >> 4;

    int arow = tid >> 3;
    int akk = (tid & 7) * 4;
    const float* aptr = Ab + (long long)(m0 + arow) * K + akk;
    const long long astep = (long long)32 * K;

    int bk, bn;
    const float* bptr;
    bool bv0 = true, bv1 = true;
    if (TB) {
        bn = tid >> 3;
        bk = (tid & 7) * 4;
        bv0 = (n0 + bn) < N;
        bv1 = (n0 + bn + 32) < N;
        bptr = Bb + (long long)(n0 + bn) * K + bk;
    } else {
        bk = (tid >> 4) * 2;
        bn = (tid & 15) * 4;
        bptr = Bb + (long long)bk * N + n0 + bn;
    }

    float4 pa[4], pb[2];
#pragma unroll
    for (int i = 0; i < 4; i++) pa[i] = *(const float4*)(aptr + i * astep);
    if (TB) {
        pb[0] = bv0 ? *(const float4*)(bptr) : make_float4(0.f,0.f,0.f,0.f);
        pb[1] = bv1 ? *(const float4*)(bptr + astep) : make_float4(0.f,0.f,0.f,0.f);
    } else {
        pb[0] = *(const float4*)(bptr);
        pb[1] = *(const float4*)(bptr + N);
    }

    float acc[8][4] = {};

    for (int k0 = 0; k0 < K; k0 += 32) {
#pragma unroll
        for (int i = 0; i < 4; i++) {
            As[akk+0][arow+32*i] = pa[i].x;
            As[akk+1][arow+32*i] = pa[i].y;
            As[akk+2][arow+32*i] = pa[i].z;
            As[akk+3][arow+32*i] = pa[i].w;
        }
        if (TB) {
            Bs[bk+0][bn] = pb[0].x; Bs[bk+1][bn] = pb[0].y;
            Bs[bk+2][bn] = pb[0].z; Bs[bk+3][bn] = pb[0].w;
            Bs[bk+0][bn+32] = pb[1].x; Bs[bk+1][bn+32] = pb[1].y;
            Bs[bk+2][bn+32] = pb[1].z; Bs[bk+3][bn+32] = pb[1].w;
        } else {
            *(float4*)&Bs[bk][bn] = pb[0];
            *(float4*)&Bs[bk+1][bn] = pb[1];
        }
        __syncthreads();
        if (k0 + 32 < K) {
            aptr += 32;
#pragma unroll
            for (int i = 0; i < 4; i++) pa[i] = *(const float4*)(aptr + i * astep);
            if (TB) {
                bptr += 32;
                pb[0] = bv0 ? *(const float4*)(bptr) : make_float4(0.f,0.f,0.f,0.f);
                pb[1] = bv1 ? *(const float4*)(bptr + astep) : make_float4(0.f,0.f,0.f,0.f);
            } else {
                bptr += (long long)32 * N;
                pb[0] = *(const float4*)(bptr);
                pb[1] = *(const float4*)(bptr + N);
            }
        }
#pragma unroll 8
        for (int k = 0; k < 32; k++) {
            float4 a0 = *(const float4*)&As[k][ty*8];
            float4 a1 = *(const float4*)&As[k][ty*8+4];
            float4 b4 = *(const float4*)&Bs[k][tx*4];
            float a[8] = {a0.x,a0.y,a0.z,a0.w,a1.x,a1.y,a1.z,a1.w};
            float bbv[4] = {b4.x,b4.y,b4.z,b4.w};
#pragma unroll
            for (int i = 0; i < 8; i++)
#pragma unroll
                for (int j = 0; j < 4; j++)
                    acc[i][j] = fmaf(a[i], bbv[j], acc[i][j]);
        }
        __syncthreads();
    }

#pragma unroll
    for (int i = 0; i < 8; i++) {
        int m = m0 + ty*8 + i;
        float sc = 1.f, bi = 0.f;
        if (MODE == 1) { sc = scale[m] * BNF; bi = bias[m]; }
        if (MODE == 2) { bi = bias[m]; }
        int n = n0 + tx*4;
        if (!TB || n + 3 < N) {
            float v[4];
#pragma unroll
            for (int j = 0; j < 4; j++) {
                float t = acc[i][j];
                if (MODE == 1) t = fmaxf(fmaf(t, sc, bi), 0.f);
                else if (MODE == 2) t = t + bi;
                else if (MODE == 3)
                    t = t * 0.25f + extra[(long long)blockIdx.z * sE + (long long)m * N + n + j];
                v[j] = t;
            }
            float4 o = make_float4(v[0], v[1], v[2], v[3]);
            *(float4*)(Cb + (long long)m * N + n) = o;
        }
    }
}

// ------------------------- depthwise 1x7 + 7x1 fused --------------------------
__global__ void dwconv_k(const float* __restrict__ p,
                         const float* __restrict__ wh, const float* __restrict__ wv,
                         const float* __restrict__ hg, const float* __restrict__ hb,
                         const float* __restrict__ vg, const float* __restrict__ vb,
                         float* __restrict__ out)
{
    int idx = blockIdx.x * blockDim.x + threadIdx.x;
    if (idx >= BB * CC * HWW) return;
    int l = idx % HWW;
    int c = (idx / HWW) % CC;
    int y = l / WW, x = l % WW;
    const float* base = p + (idx - l);
    float sh = 0.f, sv = 0.f;
#pragma unroll
    for (int j = 0; j < 7; j++) {
        int xx = x - 3 + j;
        if (xx >= 0 && xx < WW) sh += base[y * WW + xx] * wh[c * 7 + j];
        int yy = y - 3 + j;
        if (yy >= 0 && yy < HH) sv += base[yy * WW + x] * wv[c * 7 + j];
    }
    float rh = fmaxf(sh * (hg[c] * BNF) + hb[c], 0.f);
    float rv = fmaxf(sv * (vg[c] * BNF) + vb[c], 0.f);
    out[idx] = rh + rv;
}

// ------------------------- layernorm over C -----------------------------------
__global__ void ln_stats_k(const float* __restrict__ x)
{
    int l = blockIdx.x * blockDim.x + threadIdx.x;
    int b = blockIdx.y;
    if (l >= HWW) return;
    const float* xp = x + (long long)b * CC * HWW + l;
    float s = 0.f, ss = 0.f;
#pragma unroll 8
    for (int c = 0; c < CC; c++) { float v = xp[(long long)c * HWW]; s += v; ss += v * v; }
    float mu = s * (1.f / CC);
    float var = ss * (1.f / CC) - mu * mu;
    g_mu[b * HWW + l] = mu;
    g_rstd[b * HWW + l] = rsqrtf(var + 1e-5f);
}

__global__ void trans_norm_k(const float* __restrict__ x,
                             const float* __restrict__ lng, const float* __restrict__ lnb)
{
    __shared__ float tile[32][33];
    int b = blockIdx.z;
    int l0 = blockIdx.x * 32, c0 = blockIdx.y * 32;
    int tx = threadIdx.x, ty = threadIdx.y;   // (32,8)
#pragma unroll
    for (int i = 0; i < 4; i++) {
        int c = c0 + ty + i * 8;
        tile[ty + i * 8][tx] = x[((long long)b * CC + c) * HWW + l0 + tx];
    }
    __syncthreads();
#pragma unroll
    for (int i = 0; i < 4; i++) {
        int l = l0 + ty + i * 8;
        int c = c0 + tx;
        float v = (tile[tx][ty + i * 8] - g_mu[b * HWW + l]) * g_rstd[b * HWW + l];
        g_xn[((long long)b * HWW + l) * CC + c] = v * lng[c] + lnb[c];
    }
}

// -------- causal depthwise conv1d + silu, chunked rolling window ---------------
#define CCT 64
__global__ void __launch_bounds__(512) conv1d_k(const float* __restrict__ cw,
                                                const float* __restrict__ cb)
{
    int d = threadIdx.x;     // 512
    int t0 = blockIdx.x * CCT;
    int b = blockIdx.y;
    int dir = blockIdx.z;
    float w0 = cw[d * 4 + 0], w1 = cw[d * 4 + 1], w2 = cw[d * 4 + 2], w3 = cw[d * 4 + 3];
    float bias = cb[d];
    long long bb = (long long)b * LL;
    float x0 = (t0 >= 3) ? g_xz[(bb + seq_map(dir, t0 - 3)) * 1024 + d] : 0.f;
    float x1 = (t0 >= 2) ? g_xz[(bb + seq_map(dir, t0 - 2)) * 1024 + d] : 0.f;
    float x2 = (t0 >= 1) ? g_xz[(bb + seq_map(dir, t0 - 1)) * 1024 + d] : 0.f;
    float xn = g_xz[(bb + seq_map(dir, t0)) * 1024 + d];
    float* yo = &g_xm[(((long long)dir * BB + b) * LL + t0) * DI + d];
    for (int i = 0; i < CCT; i++) {
        float xnn = (i + 1 < CCT) ? g_xz[(bb + seq_map(dir, t0 + i + 1)) * 1024 + d] : 0.f;
        float s = bias + w0 * x0 + w1 * x1 + w2 * x2 + w3 * xn;
        yo[(long long)i * DI] = silu_f(s);
        x0 = x1; x1 = x2; x2 = xn; xn = xnn;
    }
}

// ------------------------- transpose dt_w once --------------------------------
__global__ void dtwt_k(const float* __restrict__ dtw)
{
    int i = blockIdx.x * 256 + threadIdx.x;   // 8192
    int dd = i >> 4, r = i & 15;
    g_dtwT[r * DI + dd] = dtw[i];
}

// ---------- dt = softplus(proj[:,:16] @ dt_w.T + dt_b), 16 t per block --------
#define DTT 16
__global__ void __launch_bounds__(512) dt_k(const float* __restrict__ dtbias)
{
    __shared__ float pr[DTT][16];
    int d = threadIdx.x;
    int t0 = blockIdx.x * DTT;
    int b = blockIdx.y, dir = blockIdx.z;
    long long row0 = ((long long)dir * BB + b) * LL + t0;
    if (d < DTT * 16) {
        int ti = d >> 4, r = d & 15;
        pr[ti][r] = g_projm[(row0 + ti) * 48 + r];
    }
    float wreg[16];
#pragma unroll
    for (int r = 0; r < 16; r++) wreg[r] = g_dtwT[r * DI + d];
    float bias = dtbias[d];
    __syncthreads();
    float* out = &g_dtb[row0 * DI + d];
#pragma unroll 4
    for (int t = 0; t < DTT; t++) {
        float acc = bias;
#pragma unroll
        for (int r = 0; r < 16; r++) acc = fmaf(pr[t][r], wreg[r], acc);
        float dt = (acc > 15.f) ? acc : log1pf(expf(acc));
        out[(long long)t * DI] = dt;
    }
}

// ------------------------- selective scan (PF=8 pipeline) ---------------------
// warp = 2 channels x 16 states; stores y ungated (bf16) at scan index t.
__global__ void __launch_bounds__(128) scan_k(const float* __restrict__ A_log,
                                              const float* __restrict__ Dp)
{
    int tid = threadIdx.x;
    int lane = tid & 31;
    int gwarp = blockIdx.x * 4 + (tid >> 5);          // 0..2047
    int dir = gwarp >> 9;
    int b = (gwarp >> 8) & 1;
    int d = ((gwarp & 255) << 1) | (lane >> 4);
    int s = lane & 15;

    float Av = -expf(A_log[d * 16 + s]);
    float Dv = Dp[d];
    long long dbase = ((long long)dir * BB + b) * LL;
    const float* pdt = g_dtb + dbase * DI + d;
    const float* pxm = g_xm + dbase * DI + d;
    const float* pB  = g_projm + dbase * 48 + 16 + s;
    const float* pC  = g_projm + dbase * 48 + 32 + s;
    __nv_bfloat16* py = g_y + dbase * DI + d;

    const int PF = 8;
    float f_dt[PF], f_x[PF], f_B[PF], f_C[PF];
#pragma unroll
    for (int i = 0; i < PF; i++) {
        f_dt[i] = pdt[i * DI];
        f_x[i]  = pxm[i * DI];
        f_B[i]  = pB[i * 48];
        f_C[i]  = pC[i * 48];
    }
    const float* qdt = pdt + PF * DI;
    const float* qxm = pxm + PF * DI;
    const float* qB  = pB + PF * 48;
    const float* qC  = pC + PF * 48;

    float h = 0.f;
    for (int t0 = 0; t0 < LL; t0 += PF) {
        bool pf = (t0 + PF < LL);
#pragma unroll
        for (int i = 0; i < PF; i++) {
            float dtv = f_dt[i], xv = f_x[i], Bv = f_B[i], Cv = f_C[i];
            if (pf) {
                f_dt[i] = qdt[i * DI];
                f_x[i]  = qxm[i * DI];
                f_B[i]  = qB[i * 48];
                f_C[i]  = qC[i * 48];
            }
            float dA = __expf(dtv * Av);
            h = fmaf(dA, h, dtv * xv * Bv);
            float part = h * Cv;
            part += __shfl_xor_sync(0xffffffffu, part, 1);
            part += __shfl_xor_sync(0xffffffffu, part, 2);
            part += __shfl_xor_sync(0xffffffffu, part, 4);
            part += __shfl_xor_sync(0xffffffffu, part, 8);
            if (s == 0) py[i * DI] = __float2bfloat16(fmaf(Dv, xv, part));
        }
        qdt += PF * DI; qxm += PF * DI; qB += PF * 48; qC += PF * 48; py += PF * DI;
    }
}

// ----- gather 4 directions back to natural order, apply silu(z) gate ----------
__global__ void ysum_k()
{
    long long i = (long long)blockIdx.x * blockDim.x + threadIdx.x;
    if (i >= (long long)BL * DI) return;
    int d = (int)(i & (DI - 1));
    int l = (int)((i / DI) % LL);
    int b = (int)(i / ((long long)LL * DI));
    int t2 = (l % WW) * HH + l / WW;   // transpose involution (H==W==48)
    const long long st = (long long)BB * LL * DI;
    long long bb = (long long)b * LL * DI;
    float y = __bfloat162float(g_y[bb + (long long)l * DI + d])
            + __bfloat162float(g_y[st + bb + (long long)(LL - 1 - l) * DI + d])
            + __bfloat162float(g_y[2 * st + bb + (long long)t2 * DI + d])
            + __bfloat162float(g_y[3 * st + bb + (long long)(LL - 1 - t2) * DI + d]);
    float z = g_xz[((long long)b * LL + l) * 1024 + DI + d];
    g_ysum[((long long)b * LL + l) * DI + d] = y * silu_f(z);
}

// ------------------------- SE head --------------------------------------------
__global__ void mean_k()
{
    int c = blockIdx.x, b = blockIdx.y;
    long long base = ((long long)b * CC + c) * HWW;
    float s = 0.f;
    for (int l = threadIdx.x; l < HWW; l += 256)
        s += g_featloc[base + l] + g_featglob[base + l];
    __shared__ float red[256];
    red[threadIdx.x] = s;
    __syncthreads();
    for (int o = 128; o; o >>= 1) {
        if (threadIdx.x < o) red[threadIdx.x] += red[threadIdx.x + o];
        __syncthreads();
    }
    if (threadIdx.x == 0) g_sv[b * CC + c] = red[0] / (float)HWW;
}

__global__ void fc_k(const float* __restrict__ fc1, const float* __restrict__ fc2)
{
    int b = blockIdx.x;
    __shared__ float ss[CC], tt[16];
    int tid = threadIdx.x;   // 256
    ss[tid] = g_sv[b * CC + tid];
    __syncthreads();
    if (tid < 16) {
        float a = 0.f;
        for (int c = 0; c < CC; c++) a += ss[c] * fc1[tid * CC + c];
        tt[tid] = fmaxf(a, 0.f);
    }
    __syncthreads();
    float z0 = 0.f, z1 = 0.f;
#pragma unroll
    for (int m = 0; m < 16; m++) {
        z0 += tt[m] * fc2[tid * 16 + m];
        z1 += tt[m] * fc2[(CC + tid) * 16 + m];
    }
    float mx = fmaxf(z0, z1);
    float e0 = expf(z0 - mx), e1 = expf(z1 - mx);
    float w0 = e0 / (e0 + e1);
    g_wv[b * 2 * CC + tid] = w0;
    g_wv[b * 2 * CC + CC + tid] = 1.f - w0;
}

__global__ void final_k(float* __restrict__ out)
{
    long long i = (long long)blockIdx.x * 256 + threadIdx.x;
    if (i >= (long long)BB * CC * HWW) return;
    int c = (int)((i / HWW) % CC);
    int b = (int)(i / ((long long)CC * HWW));
    out[i] = g_wv[b * 2 * CC + c] * g_featloc[i] + g_wv[b * 2 * CC + CC + c] * g_featglob[i];
}

// ------------------------- launch ---------------------------------------------
extern "C" void kernel_launch(void* const* d_in, const int* in_sizes, int n_in,
                              void* d_out, int out_size)
{
    const float* x        = (const float*)d_in[0];
    const float* reduce_w = (const float*)d_in[1];
    const float* bn0_g    = (const float*)d_in[2];
    const float* bn0_b    = (const float*)d_in[3];
    const float* proj_w   = (const float*)d_in[4];
    const float* bn1_g    = (const float*)d_in[5];
    const float* bn1_b    = (const float*)d_in[6];
    const float* dwh_w    = (const float*)d_in[7];
    const float* bnh_g    = (const float*)d_in[8];
    const float* bnh_b    = (const float*)d_in[9];
    const float* dwv_w    = (const float*)d_in[10];
    const float* bnv_g    = (const float*)d_in[11];
    const float* bnv_b    = (const float*)d_in[12];
    const float* fus_w    = (const float*)d_in[13];
    const float* fus_b    = (const float*)d_in[14];
    const float* ln_g     = (const float*)d_in[15];
    const float* ln_b     = (const float*)d_in[16];
    const float* in_w     = (const float*)d_in[17];
    const float* conv_w   = (const float*)d_in[18];
    const float* conv_b   = (const float*)d_in[19];
    const float* xproj_w  = (const float*)d_in[20];
    const float* dt_w     = (const float*)d_in[21];
    const float* dt_b     = (const float*)d_in[22];
    const float* A_log    = (const float*)d_in[23];
    const float* Dp       = (const float*)d_in[24];
    const float* out_w    = (const float*)d_in[25];
    const float* fc1_w    = (const float*)d_in[26];
    const float* fc2_w    = (const float*)d_in[27];

    float *xred, *p, *hv, *featloc, *featglob, *xn, *xz, *xm, *projm, *ysum;
    cudaGetSymbolAddress((void**)&xred, g_xred);
    cudaGetSymbolAddress((void**)&p, g_p);
    cudaGetSymbolAddress((void**)&hv, g_hv);
    cudaGetSymbolAddress((void**)&featloc, g_featloc);
    cudaGetSymbolAddress((void**)&featglob, g_featglob);
    cudaGetSymbolAddress((void**)&xn, g_xn);
    cudaGetSymbolAddress((void**)&xz, g_xz);
    cudaGetSymbolAddress((void**)&xm, g_xm);
    cudaGetSymbolAddress((void**)&projm, g_projm);
    cudaGetSymbolAddress((void**)&ysum, g_ysum);

    // 1) x = relu(bn0(reduce_w @ xin))
    gemm128<1, false><<<dim3(36, 2, BB), 256>>>(reduce_w, x, xred, 256, 2304, 512,
        0, (long long)CIN * HWW, (long long)CC * HWW, bn0_g, bn0_b, (const float*)0, 0);
    // 2,3) layernorm over C (shared by all directions)
    ln_stats_k<<<dim3((HWW + 255) / 256, BB), 256>>>(xred);
    trans_norm_k<<<dim3(HWW / 32, CC / 32, BB), dim3(32, 8)>>>(xred, ln_g, ln_b);
    // 4) in_proj: xz = xn @ in_w.T  (128x128 8x8 kernel)
    gemm_nt_big<<<dim3(8, 18, BB), 256>>>(xn, in_w, xz, 2304, 1024, 256,
        (long long)LL * CC, (long long)LL * 1024);
    // 5) transpose dt_w once
    dtwt_k<<<32, 256>>>(dt_w);
    // 6) causal conv1d + silu -> scan-ordered xm (chunked)
    conv1d_k<<<dim3(LL / CCT, BB, 4), 512>>>(conv_w, conv_b);
    // 7) xproj per direction: proj = xm @ xproj_w.T
    gemm128<0, true><<<dim3(1, 18, 8), 256>>>(xm, xproj_w, projm, 2304, 48, 512,
        (long long)LL * DI, 0, (long long)LL * 48, (const float*)0, (const float*)0,
        (const float*)0, 0);
    // 8) dt = softplus(...)
    dt_k<<<dim3(LL / DTT, BB, 4), 512>>>(dt_b);
    // 9) selective scan (PF=8, bf16 y store)
    scan_k<<<512, 128>>>(A_log, Dp);
    // 10) gather directions to natural order + silu(z) gate
    ysum_k<<<(BL * DI + 255) / 256, 256>>>();
    // 11) feat_global = 0.25 * (out_w @ ysum) + x
    gemm128<3, true><<<dim3(36, 2, BB), 256>>>(out_w, ysum, featglob, 256, 2304, 512,
        0, (long long)LL * DI, (long long)CC * HWW, (const float*)0, (const float*)0,
        xred, (long long)CC * HWW);
    // 12) p = relu(bn1(proj_w @ x))   (local branch)
    gemm128<1, false><<<dim3(36, 2, BB), 256>>>(proj_w, xred, p, 256, 2304, 256,
        0, (long long)CC * HWW, (long long)CC * HWW, bn1_g, bn1_b, (const float*)0, 0);
    // 13) depthwise h+v fused
    dwconv_k<<<(BB * CC * HWW + 255) / 256, 256>>>(p, dwh_w, dwv_w,
                                                   bnh_g, bnh_b, bnv_g, bnv_b, hv);
    // 14) feat_local = fus_w @ (h+v) + fus_b
    gemm128<2, false><<<dim3(36, 2, BB), 256>>>(fus_w, hv, featloc, 256, 2304, 256,
        0, (long long)CC * HWW, (long long)CC * HWW, (const float*)0, fus_b, (const float*)0, 0);
    // 15-17) SE head + final combine
    mean_k<<<dim3(CC, BB), 256>>>();
    fc_k<<<BB, 256>>>(fc1_w, fc2_w);
    final_k<<<(BB * CC * HWW + 255) / 256, 256>>>((float*)d_out);
}